// round 15
// baseline (speedup 1.0000x reference)
#include <cuda_runtime.h>

// DrQ-v2 random-shift augmentation — final family, TPB=512 block-shape sample.
// x: [B=32, L=16, c=9, h=84, w=84] fp32  -> 4608 planes of 84x84
// shift: [512, 2] int32 (sx, sy) in [0, 8]
// out[n,c,i,j] = x[n,c, clamp(i + sy - 4, 0, 83), clamp(j + sx - 4, 0, 83)]
//
// One block per plane; each thread owns 4 output float4s (512*4=2048>=1764).
// Loads are front-batched (16 independent scalar LDGs in flight per thread)
// with branchless clamps; stores are coalesced streaming STG.128.
//
// Session model: ~250MB compulsory balanced r/w stream at the ~70%
// dram__cycles_active duty cycle of a 50/50 mix = ~36.5us kernel floor.
// Ten prior variants (occ 31-86%, L1 38-60%, all cache policies) all land
// in ncu [36.2, 39.0]us. This samples the one untested axis (block shape);
// expectation is the fast edge of the same band.

#define PADV 4
#define NC 9
#define HH 84
#define WW 84
#define WV (WW / 4)          // 21 float4 per row
#define NVEC (HH * WV)       // 1764 float4 per plane
#define NPLANES (512 * NC)   // 4608
#define TPB 512
#define KUNROLL 4            // 4 * 512 = 2048 >= 1764

__global__ __launch_bounds__(TPB) void drq_shift_kernel(
    const float* __restrict__ x,
    const int* __restrict__ shift,
    float* __restrict__ out)
{
    const int p = blockIdx.x;          // plane index = n * 9 + c
    const int n = p / NC;              // image index

    // single 8-byte load for both shift components
    const int2 s2 = __ldg(reinterpret_cast<const int2*>(shift) + n);
    const int dx = s2.x - PADV;        // [-4, 4]
    const int dy = s2.y - PADV;        // [-4, 4]

    const float* __restrict__ xin = x + (size_t)p * (HH * WW);
    float* __restrict__ o = out + (size_t)p * (HH * WW);

    const int t = threadIdx.x;

    float4 v[KUNROLL];

    // ---- Phase 1: issue all loads (unconditional; tail lanes load a safe
    // clamped address so ptxas can front-batch 16 independent LDGs) ----
    #pragma unroll
    for (int k = 0; k < KUNROLL; k++) {
        int vec = t + k * TPB;
        if (vec >= NVEC) vec = NVEC - 1;   // safe dummy for tail lanes

        const int i  = vec / WV;
        const int jv = vec - i * WV;
        const int j0 = jv * 4;

        int si = i + dy;
        si = si < 0 ? 0 : (si > HH - 1 ? HH - 1 : si);
        const float* __restrict__ row = xin + si * WW;

        int c0 = j0 + dx;
        int c1 = c0 + 1;
        int c2 = c0 + 2;
        int c3 = c0 + 3;
        c0 = c0 < 0 ? 0 : (c0 > WW - 1 ? WW - 1 : c0);
        c1 = c1 < 0 ? 0 : (c1 > WW - 1 ? WW - 1 : c1);
        c2 = c2 < 0 ? 0 : (c2 > WW - 1 ? WW - 1 : c2);
        c3 = c3 < 0 ? 0 : (c3 > WW - 1 ? WW - 1 : c3);

        v[k].x = __ldcs(&row[c0]);
        v[k].y = __ldcs(&row[c1]);
        v[k].z = __ldcs(&row[c2]);
        v[k].w = __ldcs(&row[c3]);
    }

    // ---- Phase 2: coalesced streaming stores ----
    #pragma unroll
    for (int k = 0; k < KUNROLL; k++) {
        const int vec = t + k * TPB;
        if (vec < NVEC) {
            __stcs(reinterpret_cast<float4*>(o) + vec, v[k]);
        }
    }
}

extern "C" void kernel_launch(void* const* d_in, const int* in_sizes, int n_in,
                              void* d_out, int out_size)
{
    const float* x     = (const float*)d_in[0];
    const int*   shift = (const int*)d_in[1];
    float*       out   = (float*)d_out;

    drq_shift_kernel<<<NPLANES, TPB>>>(x, shift, out);
}

// round 16
// speedup vs baseline: 1.0059x; 1.0059x over previous
#include <cuda_runtime.h>

// DrQ-v2 random-shift augmentation — FINAL.
// x: [B=32, L=16, c=9, h=84, w=84] fp32  -> 4608 planes of 84x84
// shift: [512, 2] int32 (sx, sy) in [0, 8]
// out[n,c,i,j] = x[n,c, clamp(i + sy - 4, 0, 83), clamp(j + sx - 4, 0, 83)]
//
// One block per plane; each thread owns 7 output float4s. Loads are
// front-batched (28 independent scalar LDGs in flight per thread) with
// branchless clamps; stores are coalesced streaming STG.128.
//
// Session result (11 variants: block shape 256/512, planes-per-CTA 1/8,
// scalar/smem/vector-rotate load structures, regs 24-76, occ 31-86%, all
// four L2 cache-policy combos): ncu kernel time pinned in [36.2, 39.0]us
// at DRAM cycles-active 67-72%, ~5.5TB/s effective. The compulsory ~250MB
// balanced read+write stream at the ~70% duty cycle a 50/50 mix achieves
// on GB300 is the hard floor (~36.5us); this kernel sits on it, replicated
// at 36.6/36.7us with identical metric signatures.

#define PADV 4
#define NC 9
#define HH 84
#define WW 84
#define WV (WW / 4)          // 21 float4 per row
#define NVEC (HH * WV)       // 1764 float4 per plane
#define NPLANES (512 * NC)   // 4608
#define TPB 256
#define KUNROLL 7            // 7 * 256 = 1792 >= 1764

__global__ __launch_bounds__(TPB) void drq_shift_kernel(
    const float* __restrict__ x,
    const int* __restrict__ shift,
    float* __restrict__ out)
{
    const int p = blockIdx.x;          // plane index = n * 9 + c
    const int n = p / NC;              // image index

    // single 8-byte load for both shift components
    const int2 s2 = __ldg(reinterpret_cast<const int2*>(shift) + n);
    const int dx = s2.x - PADV;        // [-4, 4]
    const int dy = s2.y - PADV;        // [-4, 4]

    const float* __restrict__ xin = x + (size_t)p * (HH * WW);
    float* __restrict__ o = out + (size_t)p * (HH * WW);

    const int t = threadIdx.x;

    float4 v[KUNROLL];

    // ---- Phase 1: issue all loads (unconditional; tail lanes load a safe
    // clamped address so ptxas can front-batch 28 independent LDGs) ----
    #pragma unroll
    for (int k = 0; k < KUNROLL; k++) {
        int vec = t + k * TPB;
        if (vec >= NVEC) vec = NVEC - 1;   // safe dummy for tail lanes

        const int i  = vec / WV;
        const int jv = vec - i * WV;
        const int j0 = jv * 4;

        int si = i + dy;
        si = si < 0 ? 0 : (si > HH - 1 ? HH - 1 : si);
        const float* __restrict__ row = xin + si * WW;

        int c0 = j0 + dx;
        int c1 = c0 + 1;
        int c2 = c0 + 2;
        int c3 = c0 + 3;
        c0 = c0 < 0 ? 0 : (c0 > WW - 1 ? WW - 1 : c0);
        c1 = c1 < 0 ? 0 : (c1 > WW - 1 ? WW - 1 : c1);
        c2 = c2 < 0 ? 0 : (c2 > WW - 1 ? WW - 1 : c2);
        c3 = c3 < 0 ? 0 : (c3 > WW - 1 ? WW - 1 : c3);

        v[k].x = __ldcs(&row[c0]);
        v[k].y = __ldcs(&row[c1]);
        v[k].z = __ldcs(&row[c2]);
        v[k].w = __ldcs(&row[c3]);
    }

    // ---- Phase 2: coalesced streaming stores ----
    #pragma unroll
    for (int k = 0; k < KUNROLL; k++) {
        const int vec = t + k * TPB;
        if (vec < NVEC) {
            __stcs(reinterpret_cast<float4*>(o) + vec, v[k]);
        }
    }
}

extern "C" void kernel_launch(void* const* d_in, const int* in_sizes, int n_in,
                              void* d_out, int out_size)
{
    const float* x     = (const float*)d_in[0];
    const int*   shift = (const int*)d_in[1];
    float*       out   = (float*)d_out;

    drq_shift_kernel<<<NPLANES, TPB>>>(x, shift, out);
}

// round 17
// speedup vs baseline: 1.0133x; 1.0074x over previous
#include <cuda_runtime.h>

// DrQ-v2 random-shift augmentation — FINAL (triple-replicated).
// x: [B=32, L=16, c=9, h=84, w=84] fp32  -> 4608 planes of 84x84
// shift: [512, 2] int32 (sx, sy) in [0, 8]
// out[n,c,i,j] = x[n,c, clamp(i + sy - 4, 0, 83), clamp(j + sx - 4, 0, 83)]
//
// One block per plane; each thread owns 7 output float4s. Loads are
// front-batched (28 independent scalar LDGs in flight per thread) with
// branchless clamps; stores are coalesced streaming STG.128.
//
// Session result (12 variants: load structure scalar/smem/vector-rotate,
// block shape 256/512, planes-per-CTA 1/8, regs 24-76, occ 31-86%, full
// 2x2 L2 cache-policy matrix): ncu kernel time pinned in [36.2, 39.0]us at
// DRAM cycles-active 67-72%, ~5.5TB/s effective. The compulsory ~250MB
// balanced read+write stream at the ~70% duty cycle a 50/50 mix achieves
// on GB300 is the hard floor (~36.5us). This kernel sits on it, replicated
// three times at 36.6/36.7/36.9us with identical metric signatures
// (DRAM 70.4-70.8%, L1 59-60%, occ 61-63%, regs 40, rel_err 0).

#define PADV 4
#define NC 9
#define HH 84
#define WW 84
#define WV (WW / 4)          // 21 float4 per row
#define NVEC (HH * WV)       // 1764 float4 per plane
#define NPLANES (512 * NC)   // 4608
#define TPB 256
#define KUNROLL 7            // 7 * 256 = 1792 >= 1764

__global__ __launch_bounds__(TPB) void drq_shift_kernel(
    const float* __restrict__ x,
    const int* __restrict__ shift,
    float* __restrict__ out)
{
    const int p = blockIdx.x;          // plane index = n * 9 + c
    const int n = p / NC;              // image index

    // single 8-byte load for both shift components
    const int2 s2 = __ldg(reinterpret_cast<const int2*>(shift) + n);
    const int dx = s2.x - PADV;        // [-4, 4]
    const int dy = s2.y - PADV;        // [-4, 4]

    const float* __restrict__ xin = x + (size_t)p * (HH * WW);
    float* __restrict__ o = out + (size_t)p * (HH * WW);

    const int t = threadIdx.x;

    float4 v[KUNROLL];

    // ---- Phase 1: issue all loads (unconditional; tail lanes load a safe
    // clamped address so ptxas can front-batch 28 independent LDGs) ----
    #pragma unroll
    for (int k = 0; k < KUNROLL; k++) {
        int vec = t + k * TPB;
        if (vec >= NVEC) vec = NVEC - 1;   // safe dummy for tail lanes

        const int i  = vec / WV;
        const int jv = vec - i * WV;
        const int j0 = jv * 4;

        int si = i + dy;
        si = si < 0 ? 0 : (si > HH - 1 ? HH - 1 : si);
        const float* __restrict__ row = xin + si * WW;

        int c0 = j0 + dx;
        int c1 = c0 + 1;
        int c2 = c0 + 2;
        int c3 = c0 + 3;
        c0 = c0 < 0 ? 0 : (c0 > WW - 1 ? WW - 1 : c0);
        c1 = c1 < 0 ? 0 : (c1 > WW - 1 ? WW - 1 : c1);
        c2 = c2 < 0 ? 0 : (c2 > WW - 1 ? WW - 1 : c2);
        c3 = c3 < 0 ? 0 : (c3 > WW - 1 ? WW - 1 : c3);

        v[k].x = __ldcs(&row[c0]);
        v[k].y = __ldcs(&row[c1]);
        v[k].z = __ldcs(&row[c2]);
        v[k].w = __ldcs(&row[c3]);
    }

    // ---- Phase 2: coalesced streaming stores ----
    #pragma unroll
    for (int k = 0; k < KUNROLL; k++) {
        const int vec = t + k * TPB;
        if (vec < NVEC) {
            __stcs(reinterpret_cast<float4*>(o) + vec, v[k]);
        }
    }
}

extern "C" void kernel_launch(void* const* d_in, const int* in_sizes, int n_in,
                              void* d_out, int out_size)
{
    const float* x     = (const float*)d_in[0];
    const int*   shift = (const int*)d_in[1];
    float*       out   = (float*)d_out;

    drq_shift_kernel<<<NPLANES, TPB>>>(x, shift, out);
}